// round 15
// baseline (speedup 1.0000x reference)
#include <cuda_runtime.h>
#include <math.h>
#include <stdint.h>

#define BATCH 128
#define HALFB 64
#define H0 128
#define W0 128
#define C1 16
#define H1 64
#define C2 32
#define H2 32
#define NCODES 512
#define DIM 32
#define TOTPX (BATCH*1024)

typedef unsigned long long u64;

// Scratch (allocation-free rule: __device__ globals)
__device__ float g_h1[BATCH*C1*H1*H1];   // after conv1+pool+gelu  [B,16,64,64]
__device__ float g_h2[BATCH*C2*H2*H2];   // after conv2+pool       [B,32,32,32]
__device__ float g_g [BATCH*C1*H1*H1];   // after up+conv3+gelu    [B,16,64,64]
__device__ float g_pe[2*TOTPX];          // per-(codehalf, px) best e
__device__ int   g_pi[2*TOTPX];          // per-(codehalf, px) best idx
__device__ double g_loss;

__device__ __forceinline__ float gelu_exact(float v) {
    return 0.5f * v * (1.0f + erff(v * 0.70710678118654752440f));
}

// ---- packed fp32x2 helpers (Blackwell FFMA2 path) -------------------------
__device__ __forceinline__ u64 pk2(float lo, float hi) {
    u64 r; asm("mov.b64 %0, {%1,%2};" : "=l"(r) : "f"(lo), "f"(hi)); return r;
}
__device__ __forceinline__ void upk2(u64 v, float& lo, float& hi) {
    asm("mov.b64 {%0,%1}, %2;" : "=f"(lo), "=f"(hi) : "l"(v));
}
__device__ __forceinline__ u64 ffma2(u64 a, u64 b, u64 c) {
    u64 d; asm("fma.rn.f32x2 %0, %1, %2, %3;" : "=l"(d) : "l"(a), "l"(b), "l"(c)); return d;
}

// ---- legacy tensor-core helpers (sm_80+ ISA, works on plain sm_100) --------
__device__ __forceinline__ uint32_t f2tf32(float v) {
    uint32_t r; asm("cvt.rna.tf32.f32 %0, %1;" : "=r"(r) : "f"(v)); return r;
}
__device__ __forceinline__ void mma_tf32(float& d0, float& d1, float& d2, float& d3,
                                         uint32_t a0, uint32_t a1, uint32_t a2, uint32_t a3,
                                         uint32_t b0, uint32_t b1) {
    asm volatile(
        "mma.sync.aligned.m16n8k8.row.col.f32.tf32.tf32.f32 "
        "{%0,%1,%2,%3}, {%4,%5,%6,%7}, {%8,%9}, {%0,%1,%2,%3};"
        : "+f"(d0), "+f"(d1), "+f"(d2), "+f"(d3)
        : "r"(a0), "r"(a1), "r"(a2), "r"(a3), "r"(b0), "r"(b1));
}

// ---------------------------------------------------------------------------
// k1: conv1 (1->16, 3x3 SAME) + maxpool2 + gelu  (oc-paired f32x2)
// ---------------------------------------------------------------------------
__global__ __launch_bounds__(256) void k1(const float* __restrict__ x,
                                          const float* __restrict__ w1,
                                          const float* __restrict__ b1, int b0) {
    __shared__ __align__(16) float s_in[34*66];
    __shared__ __align__(16) float s_w[9*C1];     // [t][oc]
    __shared__ float s_b[C1];
    const int b = blockIdx.y + b0;
    const int tile = blockIdx.x;
    const int px0 = (tile & 1) * 32;
    const int py0 = (tile >> 1) * 16;
    const int tid = threadIdx.x;
    if (tid < C1*9) { int oc = tid / 9, t = tid - oc*9; s_w[t*C1 + oc] = w1[tid]; }
    if (tid < C1)   s_b[tid] = b1[tid];
    const float* xim = x + b * (H0*W0);
    for (int i = tid; i < 34*66; i += 256) {
        int r = i / 66, c = i - r*66;
        int gy = 2*py0 - 1 + r;
        int gx = 2*px0 - 1 + c;
        float v = 0.f;
        if ((unsigned)gy < (unsigned)H0 && (unsigned)gx < (unsigned)W0)
            v = xim[gy*W0 + gx];
        s_in[i] = v;
    }
    __syncthreads();
    #pragma unroll 1
    for (int p = tid; p < 32*16; p += 256) {
        int py = p >> 5, px = p & 31;
        u64 up[4][4];
        #pragma unroll
        for (int i = 0; i < 4; i++) {
            float2 a = *(const float2*)&s_in[(2*py+i)*66 + 2*px];
            float2 c = *(const float2*)&s_in[(2*py+i)*66 + 2*px + 2];
            up[i][0] = pk2(a.x, a.x); up[i][1] = pk2(a.y, a.y);
            up[i][2] = pk2(c.x, c.x); up[i][3] = pk2(c.y, c.y);
        }
        u64 acc[8][4];
        #pragma unroll
        for (int op = 0; op < 8; op++)
            #pragma unroll
            for (int q = 0; q < 4; q++) acc[op][q] = 0ull;
        #pragma unroll
        for (int t = 0; t < 9; t++) {
            int ky = t / 3, kx = t - ky*3;
            ulonglong2 wA = *(const ulonglong2*)&s_w[t*C1 + 0];
            ulonglong2 wB = *(const ulonglong2*)&s_w[t*C1 + 4];
            ulonglong2 wC = *(const ulonglong2*)&s_w[t*C1 + 8];
            ulonglong2 wD = *(const ulonglong2*)&s_w[t*C1 + 12];
            u64 wv[8] = {wA.x, wA.y, wB.x, wB.y, wC.x, wC.y, wD.x, wD.y};
            #pragma unroll
            for (int op = 0; op < 8; op++)
                #pragma unroll
                for (int dy = 0; dy < 2; dy++)
                    #pragma unroll
                    for (int dx = 0; dx < 2; dx++)
                        acc[op][dy*2+dx] = ffma2(up[dy+ky][dx+kx], wv[op], acc[op][dy*2+dx]);
        }
        int gy = py0 + py, gx = px0 + px;
        #pragma unroll
        for (int op = 0; op < 8; op++) {
            float l0,h0,l1,h1,l2,h2,l3,h3;
            upk2(acc[op][0], l0, h0); upk2(acc[op][1], l1, h1);
            upk2(acc[op][2], l2, h2); upk2(acc[op][3], l3, h3);
            float mlo = fmaxf(fmaxf(l0,l1), fmaxf(l2,l3)) + s_b[op*2+0];
            float mhi = fmaxf(fmaxf(h0,h1), fmaxf(h2,h3)) + s_b[op*2+1];
            g_h1[((b*C1+op*2+0)*H1 + gy)*H1 + gx] = gelu_exact(mlo);
            g_h1[((b*C1+op*2+1)*H1 + gy)*H1 + gx] = gelu_exact(mhi);
        }
    }
}

// ---------------------------------------------------------------------------
// k2: conv2 (16->32, 3x3 SAME) + maxpool2  (oc-paired f32x2, 2 passes)
// ---------------------------------------------------------------------------
#define K2_SMEM ((16*18*66 + 16*9*32 + 32)*4)
__global__ __launch_bounds__(256) void k2(const float* __restrict__ w2,
                                          const float* __restrict__ b2, int b0) {
    extern __shared__ __align__(16) float sm2[];
    float* s_in = sm2;
    float* s_w  = sm2 + 16*18*66;      // [ic][t][oc]
    float* s_b  = s_w + 16*9*32;
    const int b = blockIdx.y + b0;
    const int ry0 = blockIdx.x * 8;
    const int tid = threadIdx.x;
    for (int i = tid; i < 32*16*9; i += 256) {
        int o = i / 144; int rem = i - o*144; int ic = rem / 9; int t = rem - ic*9;
        s_w[(ic*9 + t)*32 + o] = w2[i];
    }
    if (tid < 32) s_b[tid] = b2[tid];
    for (int i = tid; i < 16*18*66; i += 256) {
        int ic = i / (18*66);
        int rem = i - ic*(18*66);
        int r = rem / 66, c = rem - r*66;
        int gy = 2*ry0 - 1 + r, gx = c - 1;
        float v = 0.f;
        if ((unsigned)gy < 64u && (unsigned)gx < 64u)
            v = g_h1[((b*16+ic)*64 + gy)*64 + gx];
        s_in[i] = v;
    }
    __syncthreads();
    const int py = tid >> 5, px = tid & 31;
    const int gy = ry0 + py, gx = px;
    #pragma unroll 1
    for (int pass = 0; pass < 2; pass++) {
        u64 acc[8][4];
        #pragma unroll
        for (int op = 0; op < 8; op++)
            #pragma unroll
            for (int q = 0; q < 4; q++) acc[op][q] = 0ull;
        #pragma unroll 1
        for (int ic = 0; ic < 16; ic++) {
            const float* base = &s_in[(ic*18 + 2*py)*66 + 2*px];
            u64 up[4][4];
            #pragma unroll
            for (int i = 0; i < 4; i++) {
                float2 a = *(const float2*)&base[i*66];
                float2 c = *(const float2*)&base[i*66 + 2];
                up[i][0] = pk2(a.x, a.x); up[i][1] = pk2(a.y, a.y);
                up[i][2] = pk2(c.x, c.x); up[i][3] = pk2(c.y, c.y);
            }
            #pragma unroll
            for (int t = 0; t < 9; t++) {
                int ky = t / 3, kx = t - ky*3;
                const float* wp = &s_w[(ic*9 + t)*32 + pass*16];
                ulonglong2 wA = *(const ulonglong2*)&wp[0];
                ulonglong2 wB = *(const ulonglong2*)&wp[4];
                ulonglong2 wC = *(const ulonglong2*)&wp[8];
                ulonglong2 wD = *(const ulonglong2*)&wp[12];
                u64 wv[8] = {wA.x, wA.y, wB.x, wB.y, wC.x, wC.y, wD.x, wD.y};
                #pragma unroll
                for (int op = 0; op < 8; op++)
                    #pragma unroll
                    for (int dy = 0; dy < 2; dy++)
                        #pragma unroll
                        for (int dx = 0; dx < 2; dx++)
                            acc[op][dy*2+dx] = ffma2(up[dy+ky][dx+kx], wv[op], acc[op][dy*2+dx]);
            }
        }
        #pragma unroll
        for (int op = 0; op < 8; op++) {
            float l0,h0,l1,h1,l2,h2,l3,h3;
            upk2(acc[op][0], l0, h0); upk2(acc[op][1], l1, h1);
            upk2(acc[op][2], l2, h2); upk2(acc[op][3], l3, h3);
            int oc = pass*16 + op*2;
            float mlo = fmaxf(fmaxf(l0,l1), fmaxf(l2,l3)) + s_b[oc+0];
            float mhi = fmaxf(fmaxf(h0,h1), fmaxf(h2,h3)) + s_b[oc+1];
            g_h2[((b*32+oc+0)*32 + gy)*32 + gx] = mlo;
            g_h2[((b*32+oc+1)*32 + gy)*32 + gx] = mhi;
        }
    }
}

// ---------------------------------------------------------------------------
// k3m: VQ partial kernel. Block = 128 px x 256 codes (code half ch = bx&1).
// smem 113,664 B + <=64 regs (launch_bounds(512,2)) -> 2 blocks/SM = 32 warps.
// warp = 16-px strip (w>>1) x 128-code quarter (w&1); single-tile 3-chain MMA.
// Emits per-(codehalf, px) best (e, global idx) to gmem; k3f combines.
// ---------------------------------------------------------------------------
#define ST36 36
#define O_CBH 0
#define O_CBL (256*ST36)
#define O_ZH  (2*256*ST36)
#define O_ZL  (O_ZH + 128*ST36)
#define O_CN2 (O_ZL + 128*ST36)
#define O_RE  (O_CN2 + 256)
#define O_RI  (O_RE + 256)
#define K3M_SMEM ((O_RI + 256)*4)

__global__ __launch_bounds__(512, 2) void k3m(const float* __restrict__ codebook,
                                              int p0ofs) {
    extern __shared__ __align__(16) float smf[];
    uint32_t* smu = (uint32_t*)smf;
    const int tid = threadIdx.x;
    const int bx = blockIdx.x;
    const int pg = bx >> 1, ch = bx & 1;
    const int P0 = p0ofs + pg * 128;          // 128 px, same image
    const int C0 = ch * 256;                   // this block's code half
    const int b  = P0 >> 10;
    const int n0 = P0 & 1023;

    // stage codebook half hi/lo (tf32 split), stride 36
    for (int i = tid; i < 256*DIM; i += 512) {
        int k = i >> 5, d = i & 31;
        float v = codebook[(C0 + k)*DIM + d];
        uint32_t hb = f2tf32(v);
        float hf = __uint_as_float(hb);
        uint32_t lb = f2tf32(v - hf);
        smu[O_CBH + k*ST36 + d] = hb;
        smu[O_CBL + k*ST36 + d] = lb;
    }
    // stage z hi/lo (128 px)
    for (int i = tid; i < 128*DIM; i += 512) {
        int d = i >> 7, px = i & 127;
        float v = g_h2[(b*C2 + d)*1024 + n0 + px];
        uint32_t hb = f2tf32(v);
        float hf = __uint_as_float(hb);
        uint32_t lb = f2tf32(v - hf);
        smu[O_ZH + px*ST36 + d] = hb;
        smu[O_ZL + px*ST36 + d] = lb;
    }
    __syncthreads();
    if (tid < 256) {
        float s = 0.f;
        #pragma unroll
        for (int d = 0; d < DIM; d++) {
            float c = smf[O_CBH + tid*ST36 + d] + smf[O_CBL + tid*ST36 + d];
            s = fmaf(c, c, s);
        }
        smf[O_CN2 + tid] = 0.5f * s;
    }
    __syncthreads();

    const int w = tid >> 5, lane = tid & 31;
    const int qr = lane >> 2, qc = lane & 3;
    const int strip = w >> 1, ch2 = w & 1;
    const int m0 = strip * 16;

    // resident A fragments: z hi/lo for 4 k-steps
    uint32_t ah[4][4], al[4][4];
    #pragma unroll
    for (int kk = 0; kk < 4; kk++) {
        int kb = kk*8;
        const uint32_t* zh0 = &smu[O_ZH + (m0+qr)*ST36 + kb + qc];
        const uint32_t* zh8 = &smu[O_ZH + (m0+qr+8)*ST36 + kb + qc];
        const uint32_t* zl0 = &smu[O_ZL + (m0+qr)*ST36 + kb + qc];
        const uint32_t* zl8 = &smu[O_ZL + (m0+qr+8)*ST36 + kb + qc];
        ah[kk][0] = zh0[0]; ah[kk][1] = zh8[0]; ah[kk][2] = zh0[4]; ah[kk][3] = zh8[4];
        al[kk][0] = zl0[0]; al[kk][1] = zl8[0]; al[kk][2] = zl0[4]; al[kk][3] = zl8[4];
    }

    float bestA = 3.4e38f, bestB = 3.4e38f;
    int biA = 0x7fffffff, biB = 0x7fffffff;

    #pragma unroll 1
    for (int t = 0; t < 16; t++) {              // 16 tiles = this warp's 128 codes
        const int c0l = ch2*128 + t*8;           // local code base in [0,256)
        const uint32_t* cbh = &smu[O_CBH + (c0l+qr)*ST36 + qc];
        const uint32_t* cbl = &smu[O_CBL + (c0l+qr)*ST36 + qc];
        float hh0=0.f,hh1=0.f,hh2=0.f,hh3=0.f;
        float hl0=0.f,hl1=0.f,hl2=0.f,hl3=0.f;
        float lh0=0.f,lh1=0.f,lh2=0.f,lh3=0.f;
        #pragma unroll
        for (int kk = 0; kk < 4; kk++) {
            uint32_t bh0 = cbh[kk*8], bh1 = cbh[kk*8 + 4];
            uint32_t bl0 = cbl[kk*8], bl1 = cbl[kk*8 + 4];
            mma_tf32(hh0,hh1,hh2,hh3, ah[kk][0],ah[kk][1],ah[kk][2],ah[kk][3], bh0,bh1);
            mma_tf32(hl0,hl1,hl2,hl3, ah[kk][0],ah[kk][1],ah[kk][2],ah[kk][3], bl0,bl1);
            mma_tf32(lh0,lh1,lh2,lh3, al[kk][0],al[kk][1],al[kk][2],al[kk][3], bh0,bh1);
        }
        float d0 = hh0 + (hl0 + lh0);
        float d1 = hh1 + (hl1 + lh1);
        float d2 = hh2 + (hl2 + lh2);
        float d3 = hh3 + (hl3 + lh3);
        const int ce = c0l + 2*qc;
        float cnE = smf[O_CN2 + ce], cnO = smf[O_CN2 + ce + 1];
        const int gE = C0 + ce, gO = gE + 1;     // global code indices
        float e;
        e = cnE - d0; if (e < bestA) { bestA = e; biA = gE; }
        e = cnO - d1; if (e < bestA) { bestA = e; biA = gO; }
        e = cnE - d2; if (e < bestB) { bestB = e; biB = gE; }
        e = cnO - d3; if (e < bestB) { bestB = e; biB = gO; }
    }
    // quad reduce across qc (exact: tie -> smaller index)
    #pragma unroll
    for (int off = 1; off <= 2; off <<= 1) {
        float eA = __shfl_xor_sync(0xffffffffu, bestA, off);
        int   iA = __shfl_xor_sync(0xffffffffu, biA, off);
        if (eA < bestA || (eA == bestA && iA < biA)) { bestA = eA; biA = iA; }
        float eB = __shfl_xor_sync(0xffffffffu, bestB, off);
        int   iB = __shfl_xor_sync(0xffffffffu, biB, off);
        if (eB < bestB || (eB == bestB && iB < biB)) { bestB = eB; biB = iB; }
    }
    float* s_re = &smf[O_RE];
    int*   s_ri = (int*)&smf[O_RI];
    if (qc == 0) {
        s_re[ch2*128 + m0 + qr]     = bestA;
        s_ri[ch2*128 + m0 + qr]     = biA;
        s_re[ch2*128 + m0 + 8 + qr] = bestB;
        s_ri[ch2*128 + m0 + 8 + qr] = biB;
    }
    __syncthreads();

    // combine 2 warp-quarters per px; emit this code-half's partial to gmem
    if (tid < 128) {
        float e0 = s_re[tid], e1 = s_re[128 + tid];
        int   i0 = s_ri[tid], i1 = s_ri[128 + tid];
        int   fi = (e1 < e0 || (e1 == e0 && i1 < i0)) ? i1 : i0;
        float fe = (e1 < e0) ? e1 : e0;
        g_pe[ch*TOTPX + P0 + tid] = fe;
        g_pi[ch*TOTPX + P0 + tid] = fi;
    }
}

// ---------------------------------------------------------------------------
// k3f: combine the two code-half partials per px (lexicographic (e, idx) —
// exact argmin), write indices, compute commit loss from ORIGINAL fp32 data.
// grid 512 x 256 threads.
// ---------------------------------------------------------------------------
__global__ __launch_bounds__(256) void k3f(const float* __restrict__ codebook,
                                           float* __restrict__ out_idx) {
    const int tid = threadIdx.x;
    const int px = blockIdx.x * 256 + tid;
    float e0 = g_pe[px],        e1 = g_pe[TOTPX + px];
    int   i0 = g_pi[px],        i1 = g_pi[TOTPX + px];
    int   fi = (e1 < e0 || (e1 == e0 && i1 < i0)) ? i1 : i0;
    out_idx[px] = (float)fi;
    const int b = px >> 10, n = px & 1023;
    float cl = 0.f;
    #pragma unroll
    for (int d = 0; d < DIM; d++) {
        float zv = g_h2[(b*C2 + d)*1024 + n];
        float cv = codebook[fi*DIM + d];
        float df = cv - zv;
        cl = fmaf(df, df, cl);
    }
    #pragma unroll
    for (int off = 16; off; off >>= 1) cl += __shfl_down_sync(0xffffffffu, cl, off);
    __shared__ float wsum[8];
    if ((tid & 31) == 0) wsum[tid >> 5] = cl;
    __syncthreads();
    if (tid == 0) {
        float s = 0.f;
        #pragma unroll
        for (int ww = 0; ww < 8; ww++) s += wsum[ww];
        atomicAdd(&g_loss, (double)s);
    }
}

// ---------------------------------------------------------------------------
// k4: nearest-upsample2(h2) + conv3 (32->16) + gelu (R11 version)
// ---------------------------------------------------------------------------
#define K4_SMEM ((32*18*18 + 32*9*16 + 16)*4)
__global__ __launch_bounds__(256) void k4(const float* __restrict__ w3,
                                          const float* __restrict__ b3, int b0) {
    extern __shared__ __align__(16) float sm4[];
    float* s_h = sm4;
    float* s_w = sm4 + 32*18*18;     // [ic][t][oc]
    float* s_b = s_w + 32*9*16;
    const int b = blockIdx.y + b0;
    const int tile = blockIdx.x;
    const int oy = (tile >> 1) * 32, ox = (tile & 1) * 32;
    const int hy0 = oy/2 - 1, hx0 = ox/2 - 1;
    const int tid = threadIdx.y*16 + threadIdx.x;
    for (int i = tid; i < 16*32*9; i += 256) {
        int o = i / 288; int rem = i - o*288; int ic = rem / 9; int t = rem - ic*9;
        s_w[(ic*9 + t)*16 + o] = w3[i];
    }
    if (tid < 16) s_b[tid] = b3[tid];
    for (int i = tid; i < 32*18*18; i += 256) {
        int ic = i / 324;
        int rem = i - ic*324;
        int r = rem / 18, c = rem - r*18;
        int hy = hy0 + r, hx = hx0 + c;
        float v = 0.f;
        if ((unsigned)hy < 32u && (unsigned)hx < 32u)
            v = g_h2[((b*32+ic)*32 + hy)*32 + hx];
        s_h[i] = v;
    }
    __syncthreads();
    const int ty = threadIdx.y, tx = threadIdx.x;
    const int y0 = oy + 2*ty, x0 = ox + 2*tx;
    const int map[4] = {0, 1, 1, 2};
    u64 acc[8][4];
    #pragma unroll
    for (int op = 0; op < 8; op++)
        #pragma unroll
        for (int q = 0; q < 4; q++) acc[op][q] = 0ull;
    #pragma unroll 1
    for (int ic = 0; ic < 32; ic++) {
        u64 vp[3][3];
        #pragma unroll
        for (int a = 0; a < 3; a++)
            #pragma unroll
            for (int c = 0; c < 3; c++) {
                float v = s_h[(ic*18 + ty + a)*18 + tx + c];
                vp[a][c] = pk2(v, v);
            }
        #pragma unroll
        for (int t = 0; t < 9; t++) {
            int ky = t / 3, kx = t - ky*3;
            const float* wp = &s_w[(ic*9 + t)*16];
            ulonglong2 wA = *(const ulonglong2*)&wp[0];
            ulonglong2 wB = *(const ulonglong2*)&wp[4];
            ulonglong2 wC = *(const ulonglong2*)&wp[8];
            ulonglong2 wD = *(const ulonglong2*)&wp[12];
            u64 wv[8] = {wA.x, wA.y, wB.x, wB.y, wC.x, wC.y, wD.x, wD.y};
            #pragma unroll
            for (int op = 0; op < 8; op++)
                #pragma unroll
                for (int dy = 0; dy < 2; dy++)
                    #pragma unroll
                    for (int dx = 0; dx < 2; dx++)
                        acc[op][dy*2+dx] = ffma2(vp[map[dy+ky]][map[dx+kx]], wv[op], acc[op][dy*2+dx]);
        }
    }
    #pragma unroll
    for (int op = 0; op < 8; op++) {
        int oc = op*2;
        float blo = s_b[oc], bhi = s_b[oc+1];
        #pragma unroll
        for (int dy = 0; dy < 2; dy++)
            #pragma unroll
            for (int dx = 0; dx < 2; dx++) {
                float lo, hi;
                upk2(acc[op][dy*2+dx], lo, hi);
                g_g[((b*16+oc+0)*64 + (y0+dy))*64 + (x0+dx)] = gelu_exact(lo + blo);
                g_g[((b*16+oc+1)*64 + (y0+dy))*64 + (x0+dx)] = gelu_exact(hi + bhi);
            }
    }
}

// ---------------------------------------------------------------------------
// k5: nearest-upsample2(g) + conv4 (16->1) + clip (R11 px-paired f32x2)
// ---------------------------------------------------------------------------
__global__ __launch_bounds__(256) void k5(const float* __restrict__ w4,
                                          const float* __restrict__ b4,
                                          float* __restrict__ out, int b0) {
    __shared__ float s_g[16*18*18];
    __shared__ __align__(8) float s_w2[144*2];
    __shared__ float s_bb[1];
    const int b = blockIdx.y + b0;
    const int tile = blockIdx.x;
    const int oy = (tile >> 2) * 32, ox = (tile & 3) * 32;
    const int gy0 = oy/2 - 1, gx0 = ox/2 - 1;
    const int tid = threadIdx.y*16 + threadIdx.x;
    if (tid < 144) { float wv = w4[tid]; s_w2[tid*2] = wv; s_w2[tid*2+1] = wv; }
    if (tid == 0) s_bb[0] = b4[0];
    for (int i = tid; i < 16*18*18; i += 256) {
        int ic = i / 324;
        int rem = i - ic*324;
        int r = rem / 18, c = rem - r*18;
        int gy = gy0 + r, gx = gx0 + c;
        float v = 0.f;
        if ((unsigned)gy < 64u && (unsigned)gx < 64u)
            v = g_g[((b*16+ic)*64 + gy)*64 + gx];
        s_g[i] = v;
    }
    __syncthreads();
    const int ty = threadIdx.y, tx = threadIdx.x;
    const int y0 = oy + 2*ty, x0 = ox + 2*tx;
    u64 acc2[2] = {0ull, 0ull};
    #pragma unroll 1
    for (int ic = 0; ic < 16; ic++) {
        float v[3][3];
        #pragma unroll
        for (int a = 0; a < 3; a++)
            #pragma unroll
            for (int c = 0; c < 3; c++)
                v[a][c] = s_g[(ic*18 + ty + a)*18 + tx + c];
        u64 p[3][3];
        #pragma unroll
        for (int a = 0; a < 3; a++) {
            p[a][0] = pk2(v[a][0], v[a][1]);
            p[a][1] = pk2(v[a][1], v[a][1]);
            p[a][2] = pk2(v[a][1], v[a][2]);
        }
        const float* w2p = &s_w2[ic*18];
        #pragma unroll
        for (int t = 0; t < 9; t++) {
            int ky = t / 3, kx = t - ky*3;
            u64 wt2 = *(const u64*)&w2p[t*2];
            int r0i = (ky == 0) ? 0 : 1;
            int r1i = (ky == 2) ? 2 : 1;
            acc2[0] = ffma2(p[r0i][kx], wt2, acc2[0]);
            acc2[1] = ffma2(p[r1i][kx], wt2, acc2[1]);
        }
    }
    float bb = s_bb[0];
    #pragma unroll
    for (int dy = 0; dy < 2; dy++) {
        float lo, hi;
        upk2(acc2[dy], lo, hi);
        out[(b*H0 + (y0+dy))*W0 + (x0+0)] = fminf(fmaxf(lo + bb, -1.f), 1.f);
        out[(b*H0 + (y0+dy))*W0 + (x0+1)] = fminf(fmaxf(hi + bb, -1.f), 1.f);
    }
}

// ---------------------------------------------------------------------------
__global__ void k_zero() { if (threadIdx.x == 0) g_loss = 0.0; }
__global__ void k_fin(float* __restrict__ out_loss) {
    if (threadIdx.x == 0)
        out_loss[0] = (float)(g_loss / (double)(BATCH * 1024 * DIM));
}

// ---------------------------------------------------------------------------
// R11 skeleton (2 streams, 64-image halves, tensor-early both). k3m is now the
// high-occupancy partial kernel (2 blocks/SM); k3f combines code halves and
// computes loss after both streams finish. 1 extra stream (guard-proven).
// ---------------------------------------------------------------------------
extern "C" void kernel_launch(void* const* d_in, const int* in_sizes, int n_in,
                              void* d_out, int out_size) {
    const float* x  = (const float*)d_in[0];
    const float* w1 = (const float*)d_in[1];
    const float* b1 = (const float*)d_in[2];
    const float* w2 = (const float*)d_in[3];
    const float* b2 = (const float*)d_in[4];
    const float* cb = (const float*)d_in[5];
    const float* w3 = (const float*)d_in[6];
    const float* b3 = (const float*)d_in[7];
    const float* w4 = (const float*)d_in[8];
    const float* b4 = (const float*)d_in[9];

    float* out      = (float*)d_out;
    float* out_idx  = out + BATCH*H0*W0;          // 2,097,152
    float* out_loss = out_idx + BATCH*H2*H2;      // +131,072

    cudaFuncSetAttribute(k2,  cudaFuncAttributeMaxDynamicSharedMemorySize, K2_SMEM);
    cudaFuncSetAttribute(k3m, cudaFuncAttributeMaxDynamicSharedMemorySize, K3M_SMEM);
    cudaFuncSetAttribute(k4,  cudaFuncAttributeMaxDynamicSharedMemorySize, K4_SMEM);

    cudaStream_t sB;
    cudaEvent_t evZ, evB;
    cudaStreamCreateWithFlags(&sB, cudaStreamNonBlocking);
    cudaEventCreateWithFlags(&evZ, cudaEventDisableTiming);
    cudaEventCreateWithFlags(&evB, cudaEventDisableTiming);

    k_zero<<<1, 32>>>();
    cudaEventRecord(evZ, 0);
    cudaStreamWaitEvent(sB, evZ, 0);

    // half A on default stream
    k1<<<dim3(8, HALFB), 256>>>(x, w1, b1, 0);
    k2<<<dim3(4, HALFB), 256, K2_SMEM>>>(w2, b2, 0);
    k3m<<<1024, 512, K3M_SMEM>>>(cb, 0);
    k4<<<dim3(4, HALFB), dim3(16,16), K4_SMEM>>>(w3, b3, 0);
    k5<<<dim3(16, HALFB), dim3(16,16)>>>(w4, b4, out, 0);

    // half B on side stream
    k1<<<dim3(8, HALFB), 256, 0, sB>>>(x, w1, b1, HALFB);
    k2<<<dim3(4, HALFB), 256, K2_SMEM, sB>>>(w2, b2, HALFB);
    k3m<<<1024, 512, K3M_SMEM, sB>>>(cb, HALFB*1024);
    k4<<<dim3(4, HALFB), dim3(16,16), K4_SMEM, sB>>>(w3, b3, HALFB);
    k5<<<dim3(16, HALFB), dim3(16,16), 0, sB>>>(w4, b4, out, HALFB);
    cudaEventRecord(evB, sB);

    // combine + finalize after both halves
    cudaStreamWaitEvent(0, evB, 0);
    k3f<<<512, 256>>>(cb, out_idx);
    k_fin<<<1, 32>>>(out_loss);
}

// round 16
// speedup vs baseline: 1.0211x; 1.0211x over previous
#include <cuda_runtime.h>
#include <math.h>
#include <stdint.h>

#define BATCH 128
#define HALFB 64
#define H0 128
#define W0 128
#define C1 16
#define H1 64
#define C2 32
#define H2 32
#define NCODES 512
#define DIM 32

typedef unsigned long long u64;

// Scratch (allocation-free rule: __device__ globals)
__device__ float g_h1[BATCH*C1*H1*H1];   // after conv1+pool+gelu  [B,16,64,64]
__device__ float g_h2[BATCH*C2*H2*H2];   // after conv2+pool       [B,32,32,32]
__device__ float g_g [BATCH*C1*H1*H1];   // after up+conv3+gelu    [B,16,64,64]
__device__ __align__(16) float g_cbh[NCODES*36];  // tf32-hi codebook, stride-36 layout
__device__ __align__(16) float g_cbl[NCODES*36];  // tf32-lo codebook, stride-36 layout
__device__ double g_loss;

__device__ __forceinline__ float gelu_exact(float v) {
    return 0.5f * v * (1.0f + erff(v * 0.70710678118654752440f));
}

// ---- packed fp32x2 helpers (Blackwell FFMA2 path) -------------------------
__device__ __forceinline__ u64 pk2(float lo, float hi) {
    u64 r; asm("mov.b64 %0, {%1,%2};" : "=l"(r) : "f"(lo), "f"(hi)); return r;
}
__device__ __forceinline__ void upk2(u64 v, float& lo, float& hi) {
    asm("mov.b64 {%0,%1}, %2;" : "=f"(lo), "=f"(hi) : "l"(v));
}
__device__ __forceinline__ u64 ffma2(u64 a, u64 b, u64 c) {
    u64 d; asm("fma.rn.f32x2 %0, %1, %2, %3;" : "=l"(d) : "l"(a), "l"(b), "l"(c)); return d;
}

// ---- legacy tensor-core helpers (sm_80+ ISA, works on plain sm_100) --------
__device__ __forceinline__ uint32_t f2tf32(float v) {
    uint32_t r; asm("cvt.rna.tf32.f32 %0, %1;" : "=r"(r) : "f"(v)); return r;
}
__device__ __forceinline__ void mma_tf32(float& d0, float& d1, float& d2, float& d3,
                                         uint32_t a0, uint32_t a1, uint32_t a2, uint32_t a3,
                                         uint32_t b0, uint32_t b1) {
    asm volatile(
        "mma.sync.aligned.m16n8k8.row.col.f32.tf32.tf32.f32 "
        "{%0,%1,%2,%3}, {%4,%5,%6,%7}, {%8,%9}, {%0,%1,%2,%3};"
        : "+f"(d0), "+f"(d1), "+f"(d2), "+f"(d3)
        : "r"(a0), "r"(a1), "r"(a2), "r"(a3), "r"(b0), "r"(b1));
}

// ---------------------------------------------------------------------------
// k3p: one-shot codebook tf32 split into stride-36 device-global layout.
// ---------------------------------------------------------------------------
__global__ __launch_bounds__(256) void k3p(const float* __restrict__ codebook) {
    const int i = blockIdx.x * 256 + threadIdx.x;   // 16384 elements
    if (i < NCODES*DIM) {
        int k = i >> 5, d = i & 31;
        float v = codebook[i];
        uint32_t hb = f2tf32(v);
        float hf = __uint_as_float(hb);
        uint32_t lb = f2tf32(v - hf);
        g_cbh[k*36 + d] = __uint_as_float(hb);
        g_cbl[k*36 + d] = __uint_as_float(lb);
    }
}

// ---------------------------------------------------------------------------
// k1: conv1 (1->16, 3x3 SAME) + maxpool2 + gelu  (oc-paired f32x2)
// grid (8, HALFB); batch offset b0
// ---------------------------------------------------------------------------
__global__ __launch_bounds__(256) void k1(const float* __restrict__ x,
                                          const float* __restrict__ w1,
                                          const float* __restrict__ b1, int b0) {
    __shared__ __align__(16) float s_in[34*66];
    __shared__ __align__(16) float s_w[9*C1];     // [t][oc]
    __shared__ float s_b[C1];
    const int b = blockIdx.y + b0;
    const int tile = blockIdx.x;
    const int px0 = (tile & 1) * 32;
    const int py0 = (tile >> 1) * 16;
    const int tid = threadIdx.x;
    if (tid < C1*9) { int oc = tid / 9, t = tid - oc*9; s_w[t*C1 + oc] = w1[tid]; }
    if (tid < C1)   s_b[tid] = b1[tid];
    const float* xim = x + b * (H0*W0);
    for (int i = tid; i < 34*66; i += 256) {
        int r = i / 66, c = i - r*66;
        int gy = 2*py0 - 1 + r;
        int gx = 2*px0 - 1 + c;
        float v = 0.f;
        if ((unsigned)gy < (unsigned)H0 && (unsigned)gx < (unsigned)W0)
            v = xim[gy*W0 + gx];
        s_in[i] = v;
    }
    __syncthreads();
    #pragma unroll 1
    for (int p = tid; p < 32*16; p += 256) {
        int py = p >> 5, px = p & 31;
        u64 up[4][4];
        #pragma unroll
        for (int i = 0; i < 4; i++) {
            float2 a = *(const float2*)&s_in[(2*py+i)*66 + 2*px];
            float2 c = *(const float2*)&s_in[(2*py+i)*66 + 2*px + 2];
            up[i][0] = pk2(a.x, a.x); up[i][1] = pk2(a.y, a.y);
            up[i][2] = pk2(c.x, c.x); up[i][3] = pk2(c.y, c.y);
        }
        u64 acc[8][4];
        #pragma unroll
        for (int op = 0; op < 8; op++)
            #pragma unroll
            for (int q = 0; q < 4; q++) acc[op][q] = 0ull;
        #pragma unroll
        for (int t = 0; t < 9; t++) {
            int ky = t / 3, kx = t - ky*3;
            ulonglong2 wA = *(const ulonglong2*)&s_w[t*C1 + 0];
            ulonglong2 wB = *(const ulonglong2*)&s_w[t*C1 + 4];
            ulonglong2 wC = *(const ulonglong2*)&s_w[t*C1 + 8];
            ulonglong2 wD = *(const ulonglong2*)&s_w[t*C1 + 12];
            u64 wv[8] = {wA.x, wA.y, wB.x, wB.y, wC.x, wC.y, wD.x, wD.y};
            #pragma unroll
            for (int op = 0; op < 8; op++)
                #pragma unroll
                for (int dy = 0; dy < 2; dy++)
                    #pragma unroll
                    for (int dx = 0; dx < 2; dx++)
                        acc[op][dy*2+dx] = ffma2(up[dy+ky][dx+kx], wv[op], acc[op][dy*2+dx]);
        }
        int gy = py0 + py, gx = px0 + px;
        #pragma unroll
        for (int op = 0; op < 8; op++) {
            float l0,h0,l1,h1,l2,h2,l3,h3;
            upk2(acc[op][0], l0, h0); upk2(acc[op][1], l1, h1);
            upk2(acc[op][2], l2, h2); upk2(acc[op][3], l3, h3);
            float mlo = fmaxf(fmaxf(l0,l1), fmaxf(l2,l3)) + s_b[op*2+0];
            float mhi = fmaxf(fmaxf(h0,h1), fmaxf(h2,h3)) + s_b[op*2+1];
            g_h1[((b*C1+op*2+0)*H1 + gy)*H1 + gx] = gelu_exact(mlo);
            g_h1[((b*C1+op*2+1)*H1 + gy)*H1 + gx] = gelu_exact(mhi);
        }
    }
}

// ---------------------------------------------------------------------------
// k2: conv2 (16->32, 3x3 SAME) + maxpool2  (oc-paired f32x2, 2 passes)
// grid (4, HALFB); batch offset b0
// ---------------------------------------------------------------------------
#define K2_SMEM ((16*18*66 + 16*9*32 + 32)*4)
__global__ __launch_bounds__(256) void k2(const float* __restrict__ w2,
                                          const float* __restrict__ b2, int b0) {
    extern __shared__ __align__(16) float sm2[];
    float* s_in = sm2;
    float* s_w  = sm2 + 16*18*66;      // [ic][t][oc]
    float* s_b  = s_w + 16*9*32;
    const int b = blockIdx.y + b0;
    const int ry0 = blockIdx.x * 8;
    const int tid = threadIdx.x;
    for (int i = tid; i < 32*16*9; i += 256) {
        int o = i / 144; int rem = i - o*144; int ic = rem / 9; int t = rem - ic*9;
        s_w[(ic*9 + t)*32 + o] = w2[i];
    }
    if (tid < 32) s_b[tid] = b2[tid];
    for (int i = tid; i < 16*18*66; i += 256) {
        int ic = i / (18*66);
        int rem = i - ic*(18*66);
        int r = rem / 66, c = rem - r*66;
        int gy = 2*ry0 - 1 + r, gx = c - 1;
        float v = 0.f;
        if ((unsigned)gy < 64u && (unsigned)gx < 64u)
            v = g_h1[((b*16+ic)*64 + gy)*64 + gx];
        s_in[i] = v;
    }
    __syncthreads();
    const int py = tid >> 5, px = tid & 31;
    const int gy = ry0 + py, gx = px;
    #pragma unroll 1
    for (int pass = 0; pass < 2; pass++) {
        u64 acc[8][4];
        #pragma unroll
        for (int op = 0; op < 8; op++)
            #pragma unroll
            for (int q = 0; q < 4; q++) acc[op][q] = 0ull;
        #pragma unroll 1
        for (int ic = 0; ic < 16; ic++) {
            const float* base = &s_in[(ic*18 + 2*py)*66 + 2*px];
            u64 up[4][4];
            #pragma unroll
            for (int i = 0; i < 4; i++) {
                float2 a = *(const float2*)&base[i*66];
                float2 c = *(const float2*)&base[i*66 + 2];
                up[i][0] = pk2(a.x, a.x); up[i][1] = pk2(a.y, a.y);
                up[i][2] = pk2(c.x, c.x); up[i][3] = pk2(c.y, c.y);
            }
            #pragma unroll
            for (int t = 0; t < 9; t++) {
                int ky = t / 3, kx = t - ky*3;
                const float* wp = &s_w[(ic*9 + t)*32 + pass*16];
                ulonglong2 wA = *(const ulonglong2*)&wp[0];
                ulonglong2 wB = *(const ulonglong2*)&wp[4];
                ulonglong2 wC = *(const ulonglong2*)&wp[8];
                ulonglong2 wD = *(const ulonglong2*)&wp[12];
                u64 wv[8] = {wA.x, wA.y, wB.x, wB.y, wC.x, wC.y, wD.x, wD.y};
                #pragma unroll
                for (int op = 0; op < 8; op++)
                    #pragma unroll
                    for (int dy = 0; dy < 2; dy++)
                        #pragma unroll
                        for (int dx = 0; dx < 2; dx++)
                            acc[op][dy*2+dx] = ffma2(up[dy+ky][dx+kx], wv[op], acc[op][dy*2+dx]);
            }
        }
        #pragma unroll
        for (int op = 0; op < 8; op++) {
            float l0,h0,l1,h1,l2,h2,l3,h3;
            upk2(acc[op][0], l0, h0); upk2(acc[op][1], l1, h1);
            upk2(acc[op][2], l2, h2); upk2(acc[op][3], l3, h3);
            int oc = pass*16 + op*2;
            float mlo = fmaxf(fmaxf(l0,l1), fmaxf(l2,l3)) + s_b[oc+0];
            float mhi = fmaxf(fmaxf(h0,h1), fmaxf(h2,h3)) + s_b[oc+1];
            g_h2[((b*32+oc+0)*32 + gy)*32 + gx] = mlo;
            g_h2[((b*32+oc+1)*32 + gy)*32 + gx] = mhi;
        }
    }
}

// ---------------------------------------------------------------------------
// k3m: VQ mma.sync tf32, 3-split, 2-tile pipeline (R11 structure).
// Codebook hi/lo staged by pure float4 copy from precomputed g_cbh/g_cbl.
// 512 threads, 256 px/block; warp = 16-px strip x all 512 codes.
// grid 128 per half; pixel offset p0ofs = b0*1024.
// ---------------------------------------------------------------------------
#define ST36 36
#define O_CBH 0
#define O_CBL (NCODES*ST36)
#define O_ZH  (2*NCODES*ST36)
#define O_ZL  (O_ZH + 256*ST36)
#define O_CN2 (O_ZL + 256*ST36)
#define O_RI  (O_CN2 + NCODES)
#define K3M_SMEM ((O_RI + 256)*4)

__global__ __launch_bounds__(512) void k3m(float* __restrict__ out_idx, int p0ofs) {
    extern __shared__ __align__(16) float smf[];
    uint32_t* smu = (uint32_t*)smf;
    const int tid = threadIdx.x;
    const int P0 = p0ofs + blockIdx.x * 256;   // 256 px, same image
    const int b  = P0 >> 10;
    const int n0 = P0 & 1023;

    // stage codebook hi/lo: pure float4 copy of precomputed split (4608 f4 each)
    {
        const float4* srcH = (const float4*)g_cbh;
        const float4* srcL = (const float4*)g_cbl;
        float4* dstH = (float4*)&smf[O_CBH];
        float4* dstL = (float4*)&smf[O_CBL];
        for (int i = tid; i < NCODES*ST36/4; i += 512) {
            dstH[i] = srcH[i];
            dstL[i] = srcL[i];
        }
    }
    // stage z hi/lo (256 px), tf32 split on the fly
    for (int i = tid; i < 256*DIM; i += 512) {
        int d = i >> 8, px = i & 255;
        float v = g_h2[(b*C2 + d)*1024 + n0 + px];
        uint32_t hb = f2tf32(v);
        float hf = __uint_as_float(hb);
        uint32_t lb = f2tf32(v - hf);
        smu[O_ZH + px*ST36 + d] = hb;
        smu[O_ZL + px*ST36 + d] = lb;
    }
    __syncthreads();
    if (tid < NCODES) {
        float s = 0.f;
        #pragma unroll
        for (int d = 0; d < DIM; d++) {
            float c = smf[O_CBH + tid*ST36 + d] + smf[O_CBL + tid*ST36 + d];
            s = fmaf(c, c, s);
        }
        smf[O_CN2 + tid] = 0.5f * s;
    }
    __syncthreads();

    const int w = tid >> 5, lane = tid & 31;
    const int qr = lane >> 2, qc = lane & 3;
    const int m0 = w * 16;

    uint32_t ah[4][4], al[4][4];
    #pragma unroll
    for (int kk = 0; kk < 4; kk++) {
        int kb = kk*8;
        const uint32_t* zh0 = &smu[O_ZH + (m0+qr)*ST36 + kb + qc];
        const uint32_t* zh8 = &smu[O_ZH + (m0+qr+8)*ST36 + kb + qc];
        const uint32_t* zl0 = &smu[O_ZL + (m0+qr)*ST36 + kb + qc];
        const uint32_t* zl8 = &smu[O_ZL + (m0+qr+8)*ST36 + kb + qc];
        ah[kk][0] = zh0[0]; ah[kk][1] = zh8[0]; ah[kk][2] = zh0[4]; ah[kk][3] = zh8[4];
        al[kk][0] = zl0[0]; al[kk][1] = zl8[0]; al[kk][2] = zl0[4]; al[kk][3] = zl8[4];
    }

    float bestA = 3.4e38f, bestB = 3.4e38f;
    int biA = 0, biB = 0;

    #pragma unroll 1
    for (int t = 0; t < 64; t += 2) {
        const int c0 = t * 8;
        const int c1 = c0 + 8;
        const uint32_t* xbh = &smu[O_CBH + (c0+qr)*ST36 + qc];
        const uint32_t* xbl = &smu[O_CBL + (c0+qr)*ST36 + qc];
        const uint32_t* ybh = &smu[O_CBH + (c1+qr)*ST36 + qc];
        const uint32_t* ybl = &smu[O_CBL + (c1+qr)*ST36 + qc];
        uint32_t xh[8], xl[8], yh[8], yl[8];
        #pragma unroll
        for (int kk = 0; kk < 4; kk++) {
            xh[kk*2] = xbh[kk*8]; xh[kk*2+1] = xbh[kk*8+4];
            xl[kk*2] = xbl[kk*8]; xl[kk*2+1] = xbl[kk*8+4];
            yh[kk*2] = ybh[kk*8]; yh[kk*2+1] = ybh[kk*8+4];
            yl[kk*2] = ybl[kk*8]; yl[kk*2+1] = ybl[kk*8+4];
        }
        float xhh0=0.f,xhh1=0.f,xhh2=0.f,xhh3=0.f;
        float xhl0=0.f,xhl1=0.f,xhl2=0.f,xhl3=0.f;
        float xlh0=0.f,xlh1=0.f,xlh2=0.f,xlh3=0.f;
        float yhh0=0.f,yhh1=0.f,yhh2=0.f,yhh3=0.f;
        float yhl0=0.f,yhl1=0.f,yhl2=0.f,yhl3=0.f;
        float ylh0=0.f,ylh1=0.f,ylh2=0.f,ylh3=0.f;
        #pragma unroll
        for (int kk = 0; kk < 4; kk++) {
            mma_tf32(xhh0,xhh1,xhh2,xhh3, ah[kk][0],ah[kk][1],ah[kk][2],ah[kk][3], xh[kk*2],xh[kk*2+1]);
            mma_tf32(yhh0,yhh1,yhh2,yhh3, ah[kk][0],ah[kk][1],ah[kk][2],ah[kk][3], yh[kk*2],yh[kk*2+1]);
            mma_tf32(xhl0,xhl1,xhl2,xhl3, ah[kk][0],ah[kk][1],ah[kk][2],ah[kk][3], xl[kk*2],xl[kk*2+1]);
            mma_tf32(yhl0,yhl1,yhl2,yhl3, ah[kk][0],ah[kk][1],ah[kk][2],ah[kk][3], yl[kk*2],yl[kk*2+1]);
            mma_tf32(xlh0,xlh1,xlh2,xlh3, al[kk][0],al[kk][1],al[kk][2],al[kk][3], xh[kk*2],xh[kk*2+1]);
            mma_tf32(ylh0,ylh1,ylh2,ylh3, al[kk][0],al[kk][1],al[kk][2],al[kk][3], yh[kk*2],yh[kk*2+1]);
        }
        {
            float d0 = xhh0 + (xhl0 + xlh0);
            float d1 = xhh1 + (xhl1 + xlh1);
            float d2 = xhh2 + (xhl2 + xlh2);
            float d3 = xhh3 + (xhl3 + xlh3);
            const int ce = c0 + 2*qc;
            float2 cn = *(const float2*)&smf[O_CN2 + ce];
            float e;
            e = cn.x - d0; if (e < bestA) { bestA = e; biA = ce; }
            e = cn.y - d1; if (e < bestA) { bestA = e; biA = ce + 1; }
            e = cn.x - d2; if (e < bestB) { bestB = e; biB = ce; }
            e = cn.y - d3; if (e < bestB) { bestB = e; biB = ce + 1; }
        }
        {
            float d0 = yhh0 + (yhl0 + ylh0);
            float d1 = yhh1 + (yhl1 + ylh1);
            float d2 = yhh2 + (yhl2 + ylh2);
            float d3 = yhh3 + (yhl3 + ylh3);
            const int ce = c1 + 2*qc;
            float2 cn = *(const float2*)&smf[O_CN2 + ce];
            float e;
            e = cn.x - d0; if (e < bestA) { bestA = e; biA = ce; }
            e = cn.y - d1; if (e < bestA) { bestA = e; biA = ce + 1; }
            e = cn.x - d2; if (e < bestB) { bestB = e; biB = ce; }
            e = cn.y - d3; if (e < bestB) { bestB = e; biB = ce + 1; }
        }
    }
    #pragma unroll
    for (int off = 1; off <= 2; off <<= 1) {
        float eA = __shfl_xor_sync(0xffffffffu, bestA, off);
        int   iA = __shfl_xor_sync(0xffffffffu, biA, off);
        if (eA < bestA || (eA == bestA && iA < biA)) { bestA = eA; biA = iA; }
        float eB = __shfl_xor_sync(0xffffffffu, bestB, off);
        int   iB = __shfl_xor_sync(0xffffffffu, biB, off);
        if (eB < bestB || (eB == bestB && iB < biB)) { bestB = eB; biB = iB; }
    }
    int* s_ri = (int*)&smf[O_RI];
    if (qc == 0) {
        s_ri[m0 + qr]     = biA;
        s_ri[m0 + 8 + qr] = biB;
    }
    __syncthreads();

    float cl = 0.f;
    if (tid < 256) {
        int fi = s_ri[tid];
        out_idx[P0 + tid] = (float)fi;
        #pragma unroll
        for (int d = 0; d < DIM; d++) {
            float zv = smf[O_ZH + tid*ST36 + d] + smf[O_ZL + tid*ST36 + d];
            float cv = smf[O_CBH + fi*ST36 + d] + smf[O_CBL + fi*ST36 + d];
            float df = cv - zv;
            cl = fmaf(df, df, cl);
        }
    }
    #pragma unroll
    for (int off = 16; off; off >>= 1) cl += __shfl_down_sync(0xffffffffu, cl, off);
    __shared__ float wsum[16];
    if ((tid & 31) == 0) wsum[tid >> 5] = (tid < 256) ? cl : 0.f;
    __syncthreads();
    if (tid == 0) {
        float s = 0.f;
        #pragma unroll
        for (int ww = 0; ww < 16; ww++) s += wsum[ww];
        atomicAdd(&g_loss, (double)s);
    }
}

// ---------------------------------------------------------------------------
// k4: nearest-upsample2(h2) + conv3 (32->16) + gelu (R11 version)
// grid (4, HALFB); 32x32 tile; 2x2/thread; batch offset b0
// ---------------------------------------------------------------------------
#define K4_SMEM ((32*18*18 + 32*9*16 + 16)*4)
__global__ __launch_bounds__(256) void k4(const float* __restrict__ w3,
                                          const float* __restrict__ b3, int b0) {
    extern __shared__ __align__(16) float sm4[];
    float* s_h = sm4;
    float* s_w = sm4 + 32*18*18;     // [ic][t][oc]
    float* s_b = s_w + 32*9*16;
    const int b = blockIdx.y + b0;
    const int tile = blockIdx.x;
    const int oy = (tile >> 1) * 32, ox = (tile & 1) * 32;
    const int hy0 = oy/2 - 1, hx0 = ox/2 - 1;
    const int tid = threadIdx.y*16 + threadIdx.x;
    for (int i = tid; i < 16*32*9; i += 256) {
        int o = i / 288; int rem = i - o*288; int ic = rem / 9; int t = rem - ic*9;
        s_w[(ic*9 + t)*16 + o] = w3[i];
    }
    if (tid < 16) s_b[tid] = b3[tid];
    for (int i = tid; i < 32*18*18; i += 256) {
        int ic = i / 324;
        int rem = i - ic*324;
        int r = rem / 18, c = rem - r*18;
        int hy = hy0 + r, hx = hx0 + c;
        float v = 0.f;
        if ((unsigned)hy < 32u && (unsigned)hx < 32u)
            v = g_h2[((b*32+ic)*32 + hy)*32 + hx];
        s_h[i] = v;
    }
    __syncthreads();
    const int ty = threadIdx.y, tx = threadIdx.x;
    const int y0 = oy + 2*ty, x0 = ox + 2*tx;
    const int map[4] = {0, 1, 1, 2};
    u64 acc[8][4];
    #pragma unroll
    for (int op = 0; op < 8; op++)
        #pragma unroll
        for (int q = 0; q < 4; q++) acc[op][q] = 0ull;
    #pragma unroll 1
    for (int ic = 0; ic < 32; ic++) {
        u64 vp[3][3];
        #pragma unroll
        for (int a = 0; a < 3; a++)
            #pragma unroll
            for (int c = 0; c < 3; c++) {
                float v = s_h[(ic*18 + ty + a)*18 + tx + c];
                vp[a][c] = pk2(v, v);
            }
        #pragma unroll
        for (int t = 0; t < 9; t++) {
            int ky = t / 3, kx = t - ky*3;
            const float* wp = &s_w[(ic*9 + t)*16];
            ulonglong2 wA = *(const ulonglong2*)&wp[0];
            ulonglong2 wB = *(const ulonglong2*)&wp[4];
            ulonglong2 wC = *(const ulonglong2*)&wp[8];
            ulonglong2 wD = *(const ulonglong2*)&wp[12];
            u64 wv[8] = {wA.x, wA.y, wB.x, wB.y, wC.x, wC.y, wD.x, wD.y};
            #pragma unroll
            for (int op = 0; op < 8; op++)
                #pragma unroll
                for (int dy = 0; dy < 2; dy++)
                    #pragma unroll
                    for (int dx = 0; dx < 2; dx++)
                        acc[op][dy*2+dx] = ffma2(vp[map[dy+ky]][map[dx+kx]], wv[op], acc[op][dy*2+dx]);
        }
    }
    #pragma unroll
    for (int op = 0; op < 8; op++) {
        int oc = op*2;
        float blo = s_b[oc], bhi = s_b[oc+1];
        #pragma unroll
        for (int dy = 0; dy < 2; dy++)
            #pragma unroll
            for (int dx = 0; dx < 2; dx++) {
                float lo, hi;
                upk2(acc[op][dy*2+dx], lo, hi);
                g_g[((b*16+oc+0)*64 + (y0+dy))*64 + (x0+dx)] = gelu_exact(lo + blo);
                g_g[((b*16+oc+1)*64 + (y0+dy))*64 + (x0+dx)] = gelu_exact(hi + bhi);
            }
    }
}

// ---------------------------------------------------------------------------
// k5: nearest-upsample2(g) + conv4 (16->1) + clip (R11 px-paired f32x2)
// grid (16, HALFB); batch offset b0
// ---------------------------------------------------------------------------
__global__ __launch_bounds__(256) void k5(const float* __restrict__ w4,
                                          const float* __restrict__ b4,
                                          float* __restrict__ out, int b0) {
    __shared__ float s_g[16*18*18];
    __shared__ __align__(8) float s_w2[144*2];
    __shared__ float s_bb[1];
    const int b = blockIdx.y + b0;
    const int tile = blockIdx.x;
    const int oy = (tile >> 2) * 32, ox = (tile & 3) * 32;
    const int gy0 = oy/2 - 1, gx0 = ox/2 - 1;
    const int tid = threadIdx.y*16 + threadIdx.x;
    if (tid < 144) { float wv = w4[tid]; s_w2[tid*2] = wv; s_w2[tid*2+1] = wv; }
    if (tid == 0) s_bb[0] = b4[0];
    for (int i = tid; i < 16*18*18; i += 256) {
        int ic = i / 324;
        int rem = i - ic*324;
        int r = rem / 18, c = rem - r*18;
        int gy = gy0 + r, gx = gx0 + c;
        float v = 0.f;
        if ((unsigned)gy < 64u && (unsigned)gx < 64u)
            v = g_g[((b*16+ic)*64 + gy)*64 + gx];
        s_g[i] = v;
    }
    __syncthreads();
    const int ty = threadIdx.y, tx = threadIdx.x;
    const int y0 = oy + 2*ty, x0 = ox + 2*tx;
    u64 acc2[2] = {0ull, 0ull};
    #pragma unroll 1
    for (int ic = 0; ic < 16; ic++) {
        float v[3][3];
        #pragma unroll
        for (int a = 0; a < 3; a++)
            #pragma unroll
            for (int c = 0; c < 3; c++)
                v[a][c] = s_g[(ic*18 + ty + a)*18 + tx + c];
        u64 p[3][3];
        #pragma unroll
        for (int a = 0; a < 3; a++) {
            p[a][0] = pk2(v[a][0], v[a][1]);
            p[a][1] = pk2(v[a][1], v[a][1]);
            p[a][2] = pk2(v[a][1], v[a][2]);
        }
        const float* w2p = &s_w2[ic*18];
        #pragma unroll
        for (int t = 0; t < 9; t++) {
            int ky = t / 3, kx = t - ky*3;
            u64 wt2 = *(const u64*)&w2p[t*2];
            int r0i = (ky == 0) ? 0 : 1;
            int r1i = (ky == 2) ? 2 : 1;
            acc2[0] = ffma2(p[r0i][kx], wt2, acc2[0]);
            acc2[1] = ffma2(p[r1i][kx], wt2, acc2[1]);
        }
    }
    float bb = s_bb[0];
    #pragma unroll
    for (int dy = 0; dy < 2; dy++) {
        float lo, hi;
        upk2(acc2[dy], lo, hi);
        out[(b*H0 + (y0+dy))*W0 + (x0+0)] = fminf(fmaxf(lo + bb, -1.f), 1.f);
        out[(b*H0 + (y0+dy))*W0 + (x0+1)] = fminf(fmaxf(hi + bb, -1.f), 1.f);
    }
}

// ---------------------------------------------------------------------------
__global__ void k_zero() { if (threadIdx.x == 0) g_loss = 0.0; }
__global__ void k_fin(float* __restrict__ out_loss) {
    if (threadIdx.x == 0)
        out_loss[0] = (float)(g_loss / (double)(BATCH * 1024 * DIM));
}

// ---------------------------------------------------------------------------
// R11 skeleton (proven 401.5 µs): 2 streams, 64-image halves, both tensor-early.
// Added k3p (one-shot codebook tf32 split) before the fork so k3m staging is a
// pure float4 copy. 1 extra stream — within the allocation-guard budget.
// ---------------------------------------------------------------------------
extern "C" void kernel_launch(void* const* d_in, const int* in_sizes, int n_in,
                              void* d_out, int out_size) {
    const float* x  = (const float*)d_in[0];
    const float* w1 = (const float*)d_in[1];
    const float* b1 = (const float*)d_in[2];
    const float* w2 = (const float*)d_in[3];
    const float* b2 = (const float*)d_in[4];
    const float* cb = (const float*)d_in[5];
    const float* w3 = (const float*)d_in[6];
    const float* b3 = (const float*)d_in[7];
    const float* w4 = (const float*)d_in[8];
    const float* b4 = (const float*)d_in[9];

    float* out      = (float*)d_out;
    float* out_idx  = out + BATCH*H0*W0;          // 2,097,152
    float* out_loss = out_idx + BATCH*H2*H2;      // +131,072

    cudaFuncSetAttribute(k2,  cudaFuncAttributeMaxDynamicSharedMemorySize, K2_SMEM);
    cudaFuncSetAttribute(k3m, cudaFuncAttributeMaxDynamicSharedMemorySize, K3M_SMEM);
    cudaFuncSetAttribute(k4,  cudaFuncAttributeMaxDynamicSharedMemorySize, K4_SMEM);

    cudaStream_t sB;
    cudaEvent_t evZ, evB;
    cudaStreamCreateWithFlags(&sB, cudaStreamNonBlocking);
    cudaEventCreateWithFlags(&evZ, cudaEventDisableTiming);
    cudaEventCreateWithFlags(&evB, cudaEventDisableTiming);

    k_zero<<<1, 32>>>();
    k3p<<<64, 256>>>(cb);            // one-shot codebook split (before fork)
    cudaEventRecord(evZ, 0);
    cudaStreamWaitEvent(sB, evZ, 0);

    // half A on default stream
    k1<<<dim3(8, HALFB), 256>>>(x, w1, b1, 0);
    k2<<<dim3(4, HALFB), 256, K2_SMEM>>>(w2, b2, 0);
    k3m<<<256, 512, K3M_SMEM>>>(out_idx, 0);
    k4<<<dim3(4, HALFB), dim3(16,16), K4_SMEM>>>(w3, b3, 0);
    k5<<<dim3(16, HALFB), dim3(16,16)>>>(w4, b4, out, 0);

    // half B on side stream
    k1<<<dim3(8, HALFB), 256, 0, sB>>>(x, w1, b1, HALFB);
    k2<<<dim3(4, HALFB), 256, K2_SMEM, sB>>>(w2, b2, HALFB);
    k3m<<<256, 512, K3M_SMEM, sB>>>(out_idx, HALFB*1024);
    k4<<<dim3(4, HALFB), dim3(16,16), K4_SMEM, sB>>>(w3, b3, HALFB);
    k5<<<dim3(16, HALFB), dim3(16,16), 0, sB>>>(w4, b4, out, HALFB);
    cudaEventRecord(evB, sB);

    cudaStreamWaitEvent(0, evB, 0);
    k_fin<<<1, 32>>>(out_loss);
}